// round 15
// baseline (speedup 1.0000x reference)
#include <cuda_runtime.h>
#include <cuda_fp16.h>
#include <math.h>
#include <stdint.h>

#define TOK 32768

// ======================= scratch (no cudaMalloc allowed) =======================
__device__ __half g_img[(size_t)TOK * 512];     // LN1 out, (L,C) row-major fp16
__device__ __half g_wq [(size_t)1536 * 512];    // qkv_w^T  (N,K) fp16
__device__ __half g_wp [(size_t)512 * 512];     // proj_w^T
__device__ __half g_w1 [(size_t)2048 * 512];    // fc1_w^T
__device__ __half g_w2 [(size_t)512 * 2048];    // fc2_w^T
__device__ __half g_qkvh[(size_t)TOK * 1536];   // (L,3C) fp16 row-major
__device__ __half g_att[(size_t)TOK * 512];     // lepe+attn out, (L,C) fp16
__device__ float  g_xf [(size_t)512 * TOK];     // (C,L) fp32 col-major
__device__ __half g_h2 [(size_t)TOK * 512];     // LN2 out fp16 (L,C)
__device__ __half g_mid[(size_t)TOK * 2048];    // gelu(fc1) fp16 (L,2048)

// ======================= PTX helpers (sm_80-level only) =======================
__device__ __forceinline__ uint32_t smem_u32(const void* p) {
    uint32_t a;
    asm("{ .reg .u64 t; cvta.to.shared.u64 t, %1; cvt.u32.u64 %0, t; }" : "=r"(a) : "l"(p));
    return a;
}
__device__ __forceinline__ void ldm4(uint32_t* r, uint32_t a) {
    asm volatile("ldmatrix.sync.aligned.m8n8.x4.shared.b16 {%0,%1,%2,%3}, [%4];"
        : "=r"(r[0]), "=r"(r[1]), "=r"(r[2]), "=r"(r[3]) : "r"(a));
}
__device__ __forceinline__ void mma16816(float* d, const uint32_t* a, const uint32_t* b) {
    asm volatile("mma.sync.aligned.m16n8k16.row.col.f32.f16.f16.f32 "
        "{%0,%1,%2,%3}, {%4,%5,%6,%7}, {%8,%9}, {%0,%1,%2,%3};"
        : "+f"(d[0]), "+f"(d[1]), "+f"(d[2]), "+f"(d[3])
        : "r"(a[0]), "r"(a[1]), "r"(a[2]), "r"(a[3]), "r"(b[0]), "r"(b[1]));
}
__device__ __forceinline__ uint32_t packh2(float a, float b) {
    __half2 h = __floats2half2_rn(a, b);
    return *(uint32_t*)&h;
}
#define CP_ASYNC16(dst, src) \
    asm volatile("cp.async.cg.shared.global [%0], [%1], 16;" :: "r"(dst), "l"(src))
#define CP_COMMIT() asm volatile("cp.async.commit_group;" ::: "memory")
#define CP_WAIT1()  asm volatile("cp.async.wait_group 1;" ::: "memory")
#define CP_WAIT0()  asm volatile("cp.async.wait_group 0;" ::: "memory")

extern __shared__ char smem_raw[];

// ======================= HMMA GEMM (cp.async 2-stage, K-chunk 64, 128x256 tile) ==========
// C[M,N] = A[M,K](fp16 row-major) * Bw[N,K]^T (fp16, K contiguous per row)
// 8 warps as 2(M) x 4(N); warp tile 64x64 -> 32 independent HMMA per ldsm batch.
// EPI 1: fp32 col-major out[n*M+m] = acc + bias[n] + res[n*M+m]
// EPI 2: fp16 row-major out = gelu(acc + bias[n]), ld=ldo
// EPI 3: fp16 row-major out = acc, ld=ldo
#define TSTR 72                 // smem row stride in halves (144 B)
#define ASTG (128 * TSTR)       // A stage halves
#define BSTG (256 * TSTR)       // B stage halves
#define GEMM_SMEM_BYTES ((2 * ASTG + 2 * BSTG) * 2)   // 110592 B

template<int EPI>
__global__ __launch_bounds__(256)
void gemm_hmma(const __half* __restrict__ A, const __half* __restrict__ Bw,
               const float* __restrict__ bias, const float* __restrict__ res,
               void* __restrict__ outp, int M, int ldo, int K)
{
    const int tid  = threadIdx.x;
    const int lane = tid & 31;
    const int warp = tid >> 5;
    const int wm = warp & 1;        // 2 warps along M (64 each)
    const int wn = warp >> 1;       // 4 warps along N (64 each)
    const int m0 = blockIdx.y * 128;
    const int n0 = blockIdx.x * 256;

    float acc[4][8][4];
#pragma unroll
    for (int i = 0; i < 4; i++)
#pragma unroll
        for (int j = 0; j < 8; j++)
#pragma unroll
            for (int k = 0; k < 4; k++) acc[i][j][k] = 0.f;

    const int chunks = K >> 6;           // K-chunk = 64
    const int grow = tid >> 3;           // 0..31
    const int gcol = (tid & 7) * 8;      // halves: 8 lanes x 16B = full 128B row
    const uint32_t smb = smem_u32(smem_raw);

    auto issue = [&](int c) {
        int buf = c & 1;
        uint32_t sa = smb + (uint32_t)(buf * ASTG) * 2;
        uint32_t sb = smb + (uint32_t)(2 * ASTG + buf * BSTG) * 2;
#pragma unroll
        for (int i = 0; i < 4; i++) {
            int r = grow + i * 32;
            CP_ASYNC16(sa + (uint32_t)(r * TSTR + gcol) * 2,
                       &A[(size_t)(m0 + r) * K + c * 64 + gcol]);
        }
#pragma unroll
        for (int i = 0; i < 8; i++) {
            int r = grow + i * 32;
            CP_ASYNC16(sb + (uint32_t)(r * TSTR + gcol) * 2,
                       &Bw[(size_t)(n0 + r) * K + c * 64 + gcol]);
        }
    };

    issue(0); CP_COMMIT();
    issue(1); CP_COMMIT();

    for (int c = 0; c < chunks; c++) {
        if (c + 1 < chunks) CP_WAIT1(); else CP_WAIT0();
        __syncthreads();

        const int buf = c & 1;
        const uint32_t baseA = smb + (uint32_t)(buf * ASTG) * 2;
        const uint32_t baseB = smb + (uint32_t)(2 * ASTG + buf * BSTG) * 2;
#pragma unroll
        for (int kk = 0; kk < 4; kk++) {
            uint32_t af[4][4];
#pragma unroll
            for (int mt = 0; mt < 4; mt++) {
                int row = wm * 64 + mt * 16 + (lane & 15);
                int col = kk * 16 + ((lane >> 4) << 3);
                ldm4(af[mt], baseA + (uint32_t)(row * TSTR + col) * 2);
            }
            uint32_t bf[8][2];
#pragma unroll
            for (int pr = 0; pr < 4; pr++) {
                int row = wn * 64 + pr * 16 + ((lane >> 4) & 1) * 8 + (lane & 7);
                int col = kk * 16 + ((lane >> 3) & 1) * 8;
                uint32_t t4[4];
                ldm4(t4, baseB + (uint32_t)(row * TSTR + col) * 2);
                bf[pr * 2][0] = t4[0]; bf[pr * 2][1] = t4[1];
                bf[pr * 2 + 1][0] = t4[2]; bf[pr * 2 + 1][1] = t4[3];
            }
#pragma unroll
            for (int mt = 0; mt < 4; mt++)
#pragma unroll
                for (int nt = 0; nt < 8; nt++)
                    mma16816(acc[mt][nt], af[mt], bf[nt]);
        }
        if (c + 2 < chunks) {
            __syncthreads();          // all reads of buf done before overwrite
            issue(c + 2); CP_COMMIT();
        }
    }

    // ---------------- epilogue ----------------
#pragma unroll
    for (int mt = 0; mt < 4; mt++) {
        int r = m0 + wm * 64 + mt * 16 + (lane >> 2);
#pragma unroll
        for (int nt = 0; nt < 8; nt++) {
            int cN = n0 + wn * 64 + nt * 8 + 2 * (lane & 3);
            float v0 = acc[mt][nt][0], v1 = acc[mt][nt][1];
            float v2 = acc[mt][nt][2], v3 = acc[mt][nt][3];
            if (EPI == 1 || EPI == 2) {
                float b0 = __ldg(&bias[cN]), b1 = __ldg(&bias[cN + 1]);
                v0 += b0; v1 += b1; v2 += b0; v3 += b1;
            }
            if (EPI == 2) {
                v0 = 0.5f * v0 * (1.f + erff(v0 * 0.70710678118654752f));
                v1 = 0.5f * v1 * (1.f + erff(v1 * 0.70710678118654752f));
                v2 = 0.5f * v2 * (1.f + erff(v2 * 0.70710678118654752f));
                v3 = 0.5f * v3 * (1.f + erff(v3 * 0.70710678118654752f));
            }
            if (EPI == 1) {
                float* o = (float*)outp;
                size_t i00 = (size_t)cN * M + r;
                size_t i01 = (size_t)(cN + 1) * M + r;
                v0 += __ldg(&res[i00]);     v1 += __ldg(&res[i01]);
                v2 += __ldg(&res[i00 + 8]); v3 += __ldg(&res[i01 + 8]);
                o[i00] = v0; o[i01] = v1; o[i00 + 8] = v2; o[i01 + 8] = v3;
            } else {
                __half* o = (__half*)outp;
                *(__half2*)&o[(size_t)r * ldo + cN]       = __floats2half2_rn(v0, v1);
                *(__half2*)&o[(size_t)(r + 8) * ldo + cN] = __floats2half2_rn(v2, v3);
            }
        }
    }
}

// ======================= merged weight transpose + fp16 convert =======================
__global__ void wtrans_all(const float* __restrict__ qkvw, __half* __restrict__ wq,
                           const float* __restrict__ pw,   __half* __restrict__ wp,
                           const float* __restrict__ f1w,  __half* __restrict__ w1,
                           const float* __restrict__ f2w,  __half* __restrict__ w2)
{
    __shared__ float s[32][33];
    int b = blockIdx.x;
    const float* w; __half* wT; int K, N, t;
    if (b < 768)       { w = qkvw; wT = wq; K = 512;  N = 1536; t = b; }
    else if (b < 1024) { w = pw;   wT = wp; K = 512;  N = 512;  t = b - 768; }
    else if (b < 2048) { w = f1w;  wT = w1; K = 512;  N = 2048; t = b - 1024; }
    else               { w = f2w;  wT = w2; K = 2048; N = 512;  t = b - 2048; }
    int tx0 = N >> 5;
    int n0 = (t % tx0) * 32, k0 = (t / tx0) * 32;
    int tx = threadIdx.x, ty = threadIdx.y;
    for (int i = ty; i < 32; i += 8) s[i][tx] = w[(size_t)(k0 + i) * N + n0 + tx];
    __syncthreads();
    for (int i = ty; i < 32; i += 8) wT[(size_t)(n0 + i) * K + k0 + tx] = __float2half(s[tx][i]);
}

// ======================= LN: (C,L) fp32 -> (L,C) fp16, single gmem pass =======================
#define LNSTR 517
#define LN_SMEM_BYTES (32 * LNSTR * 4)
__global__ __launch_bounds__(256)
void ln_kernel(const float* __restrict__ in, const float* __restrict__ g,
               const float* __restrict__ b, __half* __restrict__ out)
{
    float* stg = (float*)smem_raw;     // [32][LNSTR]
    __shared__ float red[512];
    __shared__ float ms[32], rs[32];
    int tx = threadIdx.x & 31, ty = threadIdx.x >> 5;
    int tok = blockIdx.x * 32 + tx;
    float sum = 0.f, sq = 0.f;
    for (int c = ty; c < 512; c += 8) {
        float x = in[(size_t)c * TOK + tok];
        stg[tx * LNSTR + c] = x;
        sum += x; sq += x * x;
    }
    red[ty * 32 + tx] = sum; red[256 + ty * 32 + tx] = sq;
    __syncthreads();
    if (ty == 0) {
        float s = 0.f, q = 0.f;
        for (int j = 0; j < 8; j++) { s += red[j * 32 + tx]; q += red[256 + j * 32 + tx]; }
        float mean = s * (1.f / 512.f);
        float var  = q * (1.f / 512.f) - mean * mean;
        ms[tx] = mean; rs[tx] = rsqrtf(var + 1e-5f);
    }
    __syncthreads();
    size_t base = (size_t)blockIdx.x * 32 * 512;
#pragma unroll
    for (int i = 0; i < 8; i++) {
        int id = threadIdx.x + i * 256;
        int row = id >> 6, c8 = (id & 63) * 8;
        float mean = ms[row], rstd = rs[row];
        __half h[8];
#pragma unroll
        for (int j = 0; j < 8; j++) {
            int c = c8 + j;
            h[j] = __float2half((stg[row * LNSTR + c] - mean) * rstd * g[c] + b[c]);
        }
        *(uint4*)&out[base + (size_t)row * 512 + c8] = *(uint4*)h;
    }
}

// ======================= HMMA windowed attention + fused LePE =======================
// exp via ex2.approx.f16x2; half2 lepe; vs2 smem reused as lepe buffer (occupancy).
__global__ __launch_bounds__(128, 5)
void attn_hmma(const __half* __restrict__ qkv, __half* __restrict__ att,
               const float* __restrict__ w0, const float* __restrict__ b0,
               const float* __restrict__ w1, const float* __restrict__ b1)
{
    __shared__ __half qs[128 * 40];
    __shared__ __half ks[128 * 40];
    __shared__ __half vt[32 * 136];    // V transposed: [channel][token] (for PV mma)
    __shared__ __half vs2[128 * 34];   // V token-major (lepe input), then lepe output
    __shared__ __half2 swt2[144];      // conv weights [tap][chpair]
    __shared__ float sbv[32];
    const int tid = threadIdx.x;
    const int lane = tid & 31, warp = tid >> 5;
    const int bid = blockIdx.x;
    const int head = bid & 7;
    const int widx = (bid >> 3) & 255;
    const int branch = bid >> 11;
    const int d = widx >> 3, g = widx & 7;
    const int cc = branch * 256 + head * 32;

    // ---- conv weights: half2 per channel pair, [tap][pair] ----
    {
        const float* W  = branch ? w1 : w0;
        for (int idx = tid; idx < 144; idx += 128) {
            int tap = idx >> 4, p = idx & 15;
            int ch0 = head * 32 + 2 * p;
            swt2[idx] = __floats2half2_rn(W[ch0 * 9 + tap], W[(ch0 + 1) * 9 + tap]);
        }
        if (tid < 32) sbv[tid] = (branch ? b1 : b0)[head * 32 + tid];
    }

    // ---- load Q,K rows + V (both layouts) ----
    {
        int w = tid;
        int l = (branch == 0) ? d * 1024 + (w >> 2) * 32 + g * 4 + (w & 3)
                              : d * 1024 + g * 128 + w;
        const uint4* src = (const uint4*)&qkv[(size_t)l * 1536 + cc];
        uint4 qv[4], kv[4], vv[4];
#pragma unroll
        for (int i = 0; i < 4; i++) { qv[i] = src[i]; kv[i] = src[64 + i]; vv[i] = src[128 + i]; }
#pragma unroll
        for (int i = 0; i < 4; i++) {
            *(uint4*)&qs[w * 40 + i * 8] = qv[i];
            *(uint4*)&ks[w * 40 + i * 8] = kv[i];
        }
        const __half* vh = (const __half*)vv;
#pragma unroll
        for (int c = 0; c < 32; c++) vt[c * 136 + w] = vh[c];
        const __half2* vh2 = (const __half2*)vv;
#pragma unroll
        for (int i = 0; i < 16; i++) *(__half2*)&vs2[w * 34 + 2 * i] = vh2[i];
    }
    __syncthreads();

    // ---- fused LePE into registers (reads vs2) ----
    float accx[16], accy[16];
    {
        int w = tid;
        int i, j;
        const int Hs = branch ? 4 : 32;
        const int Ws = branch ? 32 : 4;
        if (branch == 0) { i = w >> 2; j = w & 3; }
        else             { i = w >> 5; j = w & 31; }
#pragma unroll
        for (int p = 0; p < 16; p++) { accx[p] = sbv[2 * p]; accy[p] = sbv[2 * p + 1]; }
        for (int di = -1; di <= 1; di++) {
            int ii = i + di;
            if (ii < 0 || ii >= Hs) continue;
            for (int dj = -1; dj <= 1; dj++) {
                int jj = j + dj;
                if (jj < 0 || jj >= Ws) continue;
                int wp = (branch == 0) ? (ii * 4 + jj) : (ii * 32 + jj);
                int tap = (di + 1) * 3 + (dj + 1);
#pragma unroll
                for (int p = 0; p < 16; p++) {
                    float2 v  = __half22float2(*(__half2*)&vs2[wp * 34 + 2 * p]);
                    float2 wt = __half22float2(swt2[tap * 16 + p]);
                    accx[p] += wt.x * v.x;
                    accy[p] += wt.y * v.y;
                }
            }
        }
    }
    __syncthreads();                    // all lepe reads of vs2 complete
    // ---- store lepe into vs2 (now "lp") ----
    {
        int w = tid;
#pragma unroll
        for (int p = 0; p < 16; p++)
            *(__half2*)&vs2[w * 34 + 2 * p] = __floats2half2_rn(accx[p], accy[p]);
    }

    const uint32_t qb = smem_u32(qs);
    const uint32_t kb = smem_u32(ks);
    const uint32_t vb = smem_u32(vt);

    uint32_t aq[2][2][4];
#pragma unroll
    for (int mt = 0; mt < 2; mt++)
#pragma unroll
        for (int kk = 0; kk < 2; kk++) {
            int row = warp * 32 + mt * 16 + (lane & 15);
            int col = kk * 16 + ((lane >> 4) << 3);
            ldm4(aq[mt][kk], qb + (uint32_t)(row * 40 + col) * 2);
        }
    __syncthreads();                    // lp stores visible to all

    float oacc[2][4][4];
#pragma unroll
    for (int i = 0; i < 2; i++)
#pragma unroll
        for (int j = 0; j < 4; j++)
#pragma unroll
            for (int k = 0; k < 4; k++) oacc[i][j][k] = 0.f;
    float lsum[2][2] = {{0.f, 0.f}, {0.f, 0.f}};
    const float c2 = 0.17677669529663687f * 1.4426950408889634f;

#pragma unroll 1
    for (int ch = 0; ch < 2; ch++) {
        float s[2][8][4];
#pragma unroll
        for (int i = 0; i < 2; i++)
#pragma unroll
            for (int j = 0; j < 8; j++)
#pragma unroll
                for (int k = 0; k < 4; k++) s[i][j][k] = 0.f;
#pragma unroll
        for (int kk = 0; kk < 2; kk++) {
            uint32_t kf[8][2];
#pragma unroll
            for (int pg = 0; pg < 4; pg++) {
                int row = ch * 64 + pg * 16 + ((lane >> 4) & 1) * 8 + (lane & 7);
                int col = kk * 16 + ((lane >> 3) & 1) * 8;
                uint32_t t4[4];
                ldm4(t4, kb + (uint32_t)(row * 40 + col) * 2);
                kf[pg * 2][0] = t4[0]; kf[pg * 2][1] = t4[1];
                kf[pg * 2 + 1][0] = t4[2]; kf[pg * 2 + 1][1] = t4[3];
            }
#pragma unroll
            for (int mt = 0; mt < 2; mt++)
#pragma unroll
                for (int nt = 0; nt < 8; nt++)
                    mma16816(s[mt][nt], aq[mt][kk], kf[nt]);
        }
        uint32_t pa[2][4][4];
#pragma unroll
        for (int mt = 0; mt < 2; mt++)
#pragma unroll
            for (int j = 0; j < 4; j++)
#pragma unroll
                for (int q2 = 0; q2 < 2; q2++) {
                    float t0 = fminf(s[mt][2 * j + q2][0] * c2, 15.f);
                    float t1 = fminf(s[mt][2 * j + q2][1] * c2, 15.f);
                    float t2 = fminf(s[mt][2 * j + q2][2] * c2, 15.f);
                    float t3 = fminf(s[mt][2 * j + q2][3] * c2, 15.f);
                    uint32_t p01 = packh2(t0, t1);
                    uint32_t p23 = packh2(t2, t3);
                    asm("ex2.approx.f16x2 %0, %1;" : "=r"(p01) : "r"(p01));
                    asm("ex2.approx.f16x2 %0, %1;" : "=r"(p23) : "r"(p23));
                    pa[mt][j][q2 * 2 + 0] = p01;
                    pa[mt][j][q2 * 2 + 1] = p23;
                    float2 f01 = __half22float2(*(__half2*)&p01);
                    float2 f23 = __half22float2(*(__half2*)&p23);
                    lsum[mt][0] += f01.x + f01.y;
                    lsum[mt][1] += f23.x + f23.y;
                }
#pragma unroll
        for (int j = 0; j < 4; j++) {
            uint32_t vf[4][2];
#pragma unroll
            for (int pg = 0; pg < 2; pg++) {
                int row = pg * 16 + ((lane >> 4) & 1) * 8 + (lane & 7);
                int col = ch * 64 + j * 16 + ((lane >> 3) & 1) * 8;
                uint32_t t4[4];
                ldm4(t4, vb + (uint32_t)(row * 136 + col) * 2);
                vf[pg * 2][0] = t4[0]; vf[pg * 2][1] = t4[1];
                vf[pg * 2 + 1][0] = t4[2]; vf[pg * 2 + 1][1] = t4[3];
            }
#pragma unroll
            for (int mt = 0; mt < 2; mt++)
#pragma unroll
                for (int nt = 0; nt < 4; nt++)
                    mma16816(oacc[mt][nt], pa[mt][j], vf[nt]);
        }
    }

#pragma unroll
    for (int mt = 0; mt < 2; mt++)
#pragma unroll
        for (int h = 0; h < 2; h++) {
            float v = lsum[mt][h];
            v += __shfl_xor_sync(0xffffffffu, v, 1);
            v += __shfl_xor_sync(0xffffffffu, v, 2);
            lsum[mt][h] = 1.f / v;
        }

#pragma unroll
    for (int mt = 0; mt < 2; mt++) {
        int w0r = warp * 32 + mt * 16 + (lane >> 2);
#pragma unroll
        for (int h = 0; h < 2; h++) {
            int w = w0r + h * 8;
            int l = (branch == 0) ? d * 1024 + (w >> 2) * 32 + g * 4 + (w & 3)
                                  : d * 1024 + g * 128 + w;
            __half* ap = att + (size_t)l * 512 + cc;
            float inv = lsum[mt][h];
#pragma unroll
            for (int nt = 0; nt < 4; nt++) {
                int col = nt * 8 + 2 * (lane & 3);
                float2 lep = __half22float2(*(__half2*)&vs2[w * 34 + col]);
                *(__half2*)(ap + col) = __floats2half2_rn(
                    lep.x + oacc[mt][nt][h * 2 + 0] * inv,
                    lep.y + oacc[mt][nt][h * 2 + 1] * inv);
            }
        }
    }
}

// ======================= launch =======================
extern "C" void kernel_launch(void* const* d_in, const int* in_sizes, int n_in,
                              void* d_out, int out_size)
{
    const float* x    = (const float*)d_in[0];
    const float* n1g  = (const float*)d_in[1];
    const float* n1b  = (const float*)d_in[2];
    const float* qkvw = (const float*)d_in[3];
    const float* l0w  = (const float*)d_in[4];
    const float* l0b  = (const float*)d_in[5];
    const float* l1w  = (const float*)d_in[6];
    const float* l1b  = (const float*)d_in[7];
    const float* pw   = (const float*)d_in[8];
    const float* pb   = (const float*)d_in[9];
    const float* n2g  = (const float*)d_in[10];
    const float* n2b  = (const float*)d_in[11];
    const float* f1w  = (const float*)d_in[12];
    const float* f1b  = (const float*)d_in[13];
    const float* f2w  = (const float*)d_in[14];
    const float* f2b  = (const float*)d_in[15];
    float* out = (float*)d_out;

    __half *img, *wq, *wp, *w1, *w2, *qkv, *att, *h2, *mid;
    float *xf;
    cudaGetSymbolAddress((void**)&img, g_img);
    cudaGetSymbolAddress((void**)&wq,  g_wq);
    cudaGetSymbolAddress((void**)&wp,  g_wp);
    cudaGetSymbolAddress((void**)&w1,  g_w1);
    cudaGetSymbolAddress((void**)&w2,  g_w2);
    cudaGetSymbolAddress((void**)&qkv, g_qkvh);
    cudaGetSymbolAddress((void**)&att, g_att);
    cudaGetSymbolAddress((void**)&xf,  g_xf);
    cudaGetSymbolAddress((void**)&h2,  g_h2);
    cudaGetSymbolAddress((void**)&mid, g_mid);

    cudaFuncSetAttribute(gemm_hmma<1>, cudaFuncAttributeMaxDynamicSharedMemorySize, GEMM_SMEM_BYTES);
    cudaFuncSetAttribute(gemm_hmma<2>, cudaFuncAttributeMaxDynamicSharedMemorySize, GEMM_SMEM_BYTES);
    cudaFuncSetAttribute(gemm_hmma<3>, cudaFuncAttributeMaxDynamicSharedMemorySize, GEMM_SMEM_BYTES);
    cudaFuncSetAttribute(ln_kernel,    cudaFuncAttributeMaxDynamicSharedMemorySize, LN_SMEM_BYTES);

    // merged weight transposes (fp32 -> fp16, (K,N) -> (N,K))
    wtrans_all<<<3072, dim3(32, 8)>>>(qkvw, wq, pw, wp, f1w, w1, f2w, w2);

    // LN1
    ln_kernel<<<TOK / 32, 256, LN_SMEM_BYTES>>>(x, n1g, n1b, img);
    // QKV GEMM -> fp16 row-major
    gemm_hmma<3><<<dim3(6, 256), 256, GEMM_SMEM_BYTES>>>(img, wq, nullptr, nullptr, qkv, TOK, 1536, 512);
    // attention with fused LePE -> att (pure store)
    attn_hmma<<<4096, 128>>>(qkv, att, l0w, l0b, l1w, l1b);
    // proj + bias + x residual -> xf (C,L) fp32
    gemm_hmma<1><<<dim3(2, 256), 256, GEMM_SMEM_BYTES>>>(att, wp, pb, x, xf, TOK, 0, 512);
    // LN2
    ln_kernel<<<TOK / 32, 256, LN_SMEM_BYTES>>>(xf, n2g, n2b, h2);
    // fc1 + bias + gelu -> mid fp16 row-major
    gemm_hmma<2><<<dim3(8, 256), 256, GEMM_SMEM_BYTES>>>(h2, w1, f1b, nullptr, mid, TOK, 2048, 512);
    // fc2 + bias + xf residual -> out (C,L) fp32
    gemm_hmma<1><<<dim3(2, 256), 256, GEMM_SMEM_BYTES>>>(mid, w2, f2b, xf, out, TOK, 0, 2048);
}

// round 16
// speedup vs baseline: 1.1421x; 1.1421x over previous
#include <cuda_runtime.h>
#include <cuda_fp16.h>
#include <math.h>
#include <stdint.h>

#define TOK 32768

// ======================= scratch (no cudaMalloc allowed) =======================
__device__ __half g_img[(size_t)TOK * 512];     // LN1 out, (L,C) row-major fp16
__device__ __half g_wq [(size_t)1536 * 512];    // qkv_w^T  (N,K) fp16
__device__ __half g_wp [(size_t)512 * 512];     // proj_w^T
__device__ __half g_w1 [(size_t)2048 * 512];    // fc1_w^T
__device__ __half g_w2 [(size_t)512 * 2048];    // fc2_w^T
__device__ __half g_qkvh[(size_t)TOK * 1536];   // (L,3C) fp16 row-major
__device__ __half g_att[(size_t)TOK * 512];     // lepe+attn out, (L,C) fp16
__device__ float  g_xf [(size_t)512 * TOK];     // (C,L) fp32 col-major
__device__ __half g_h2 [(size_t)TOK * 512];     // LN2 out fp16 (L,C)
__device__ __half g_mid[(size_t)TOK * 2048];    // gelu(fc1) fp16 (L,2048)

// ======================= PTX helpers (sm_80-level only) =======================
__device__ __forceinline__ uint32_t smem_u32(const void* p) {
    uint32_t a;
    asm("{ .reg .u64 t; cvta.to.shared.u64 t, %1; cvt.u32.u64 %0, t; }" : "=r"(a) : "l"(p));
    return a;
}
__device__ __forceinline__ void ldm4(uint32_t* r, uint32_t a) {
    asm volatile("ldmatrix.sync.aligned.m8n8.x4.shared.b16 {%0,%1,%2,%3}, [%4];"
        : "=r"(r[0]), "=r"(r[1]), "=r"(r[2]), "=r"(r[3]) : "r"(a));
}
__device__ __forceinline__ void mma16816(float* d, const uint32_t* a, const uint32_t* b) {
    asm volatile("mma.sync.aligned.m16n8k16.row.col.f32.f16.f16.f32 "
        "{%0,%1,%2,%3}, {%4,%5,%6,%7}, {%8,%9}, {%0,%1,%2,%3};"
        : "+f"(d[0]), "+f"(d[1]), "+f"(d[2]), "+f"(d[3])
        : "r"(a[0]), "r"(a[1]), "r"(a[2]), "r"(a[3]), "r"(b[0]), "r"(b[1]));
}
__device__ __forceinline__ uint32_t packh2(float a, float b) {
    __half2 h = __floats2half2_rn(a, b);
    return *(uint32_t*)&h;
}
#define CP_ASYNC16(dst, src) \
    asm volatile("cp.async.cg.shared.global [%0], [%1], 16;" :: "r"(dst), "l"(src))
#define CP_COMMIT() asm volatile("cp.async.commit_group;" ::: "memory")
#define CP_WAIT1()  asm volatile("cp.async.wait_group 1;" ::: "memory")
#define CP_WAIT0()  asm volatile("cp.async.wait_group 0;" ::: "memory")

extern __shared__ char smem_raw[];

// ======================= HMMA GEMM (cp.async 2-stage, K-chunk 64) =======================
// C[M,N] = A[M,K](fp16 row-major) * Bw[N,K]^T (fp16, K contiguous per row)
// EPI 1: fp32 col-major out[n*M+m] = acc + bias[n] + res[n*M+m]
// EPI 2: fp16 row-major out = gelu(acc + bias[n]), ld=ldo
// EPI 3: fp16 row-major out = acc, ld=ldo
#define TSTR 72                 // smem row stride in halves (144 B)
#define GSTG (128 * TSTR)       // halves per stage per matrix
#define GEMM_SMEM_BYTES (4 * GSTG * 2)   // 2 stages x (A+B) = 73728 B

template<int EPI>
__global__ __launch_bounds__(256)
void gemm_hmma(const __half* __restrict__ A, const __half* __restrict__ Bw,
               const float* __restrict__ bias, const float* __restrict__ res,
               void* __restrict__ outp, int M, int ldo, int K)
{
    const int tid  = threadIdx.x;
    const int lane = tid & 31;
    const int warp = tid >> 5;
    const int wm = warp & 1;        // 2 warps along M
    const int wn = warp >> 1;       // 4 warps along N
    const int m0 = blockIdx.y * 128;
    const int n0 = blockIdx.x * 128;

    float acc[4][4][4];
#pragma unroll
    for (int i = 0; i < 4; i++)
#pragma unroll
        for (int j = 0; j < 4; j++)
#pragma unroll
            for (int k = 0; k < 4; k++) acc[i][j][k] = 0.f;

    const int chunks = K >> 6;           // K-chunk = 64
    const int grow = tid >> 3;           // 0..31 (4 groups of 32 rows)
    const int gcol = (tid & 7) * 8;      // halves: 8 lanes x 16B = full 128B row
    const uint32_t smb = smem_u32(smem_raw);

    auto issue = [&](int c) {
        int buf = c & 1;
        uint32_t sa = smb + (uint32_t)(buf * GSTG) * 2;
        uint32_t sb = smb + (uint32_t)((2 + buf) * GSTG) * 2;
#pragma unroll
        for (int i = 0; i < 4; i++) {
            int r = grow + i * 32;
            CP_ASYNC16(sa + (uint32_t)(r * TSTR + gcol) * 2,
                       &A [(size_t)(m0 + r) * K + c * 64 + gcol]);
            CP_ASYNC16(sb + (uint32_t)(r * TSTR + gcol) * 2,
                       &Bw[(size_t)(n0 + r) * K + c * 64 + gcol]);
        }
    };

    issue(0); CP_COMMIT();
    issue(1); CP_COMMIT();

    for (int c = 0; c < chunks; c++) {
        if (c + 1 < chunks) CP_WAIT1(); else CP_WAIT0();
        __syncthreads();

        const int buf = c & 1;
        const uint32_t baseA = smb + (uint32_t)(buf * GSTG) * 2;
        const uint32_t baseB = smb + (uint32_t)((2 + buf) * GSTG) * 2;
#pragma unroll
        for (int kk = 0; kk < 4; kk++) {
            uint32_t af[4][4];
#pragma unroll
            for (int mt = 0; mt < 4; mt++) {
                int row = wm * 64 + mt * 16 + (lane & 15);
                int col = kk * 16 + ((lane >> 4) << 3);
                ldm4(af[mt], baseA + (uint32_t)(row * TSTR + col) * 2);
            }
            uint32_t bf[4][2];
#pragma unroll
            for (int pr = 0; pr < 2; pr++) {
                int row = wn * 32 + pr * 16 + ((lane >> 4) & 1) * 8 + (lane & 7);
                int col = kk * 16 + ((lane >> 3) & 1) * 8;
                uint32_t t4[4];
                ldm4(t4, baseB + (uint32_t)(row * TSTR + col) * 2);
                bf[pr * 2][0] = t4[0]; bf[pr * 2][1] = t4[1];
                bf[pr * 2 + 1][0] = t4[2]; bf[pr * 2 + 1][1] = t4[3];
            }
#pragma unroll
            for (int mt = 0; mt < 4; mt++)
#pragma unroll
                for (int nt = 0; nt < 4; nt++)
                    mma16816(acc[mt][nt], af[mt], bf[nt]);
        }
        if (c + 2 < chunks) {
            __syncthreads();          // all reads of buf done before overwrite
            issue(c + 2); CP_COMMIT();
        }
    }

    // ---------------- epilogue ----------------
#pragma unroll
    for (int mt = 0; mt < 4; mt++) {
        int r = m0 + wm * 64 + mt * 16 + (lane >> 2);
#pragma unroll
        for (int nt = 0; nt < 4; nt++) {
            int cN = n0 + wn * 32 + nt * 8 + 2 * (lane & 3);
            float v0 = acc[mt][nt][0], v1 = acc[mt][nt][1];
            float v2 = acc[mt][nt][2], v3 = acc[mt][nt][3];
            if (EPI == 1 || EPI == 2) {
                float b0 = __ldg(&bias[cN]), b1 = __ldg(&bias[cN + 1]);
                v0 += b0; v1 += b1; v2 += b0; v3 += b1;
            }
            if (EPI == 2) {
                v0 = 0.5f * v0 * (1.f + erff(v0 * 0.70710678118654752f));
                v1 = 0.5f * v1 * (1.f + erff(v1 * 0.70710678118654752f));
                v2 = 0.5f * v2 * (1.f + erff(v2 * 0.70710678118654752f));
                v3 = 0.5f * v3 * (1.f + erff(v3 * 0.70710678118654752f));
            }
            if (EPI == 1) {
                float* o = (float*)outp;
                size_t i00 = (size_t)cN * M + r;
                size_t i01 = (size_t)(cN + 1) * M + r;
                v0 += __ldg(&res[i00]);     v1 += __ldg(&res[i01]);
                v2 += __ldg(&res[i00 + 8]); v3 += __ldg(&res[i01 + 8]);
                o[i00] = v0; o[i01] = v1; o[i00 + 8] = v2; o[i01 + 8] = v3;
            } else {
                __half* o = (__half*)outp;
                *(__half2*)&o[(size_t)r * ldo + cN]       = __floats2half2_rn(v0, v1);
                *(__half2*)&o[(size_t)(r + 8) * ldo + cN] = __floats2half2_rn(v2, v3);
            }
        }
    }
}

// ======================= merged weight transpose + fp16 convert =======================
__global__ void wtrans_all(const float* __restrict__ qkvw, __half* __restrict__ wq,
                           const float* __restrict__ pw,   __half* __restrict__ wp,
                           const float* __restrict__ f1w,  __half* __restrict__ w1,
                           const float* __restrict__ f2w,  __half* __restrict__ w2)
{
    __shared__ float s[32][33];
    int b = blockIdx.x;
    const float* w; __half* wT; int K, N, t;
    if (b < 768)       { w = qkvw; wT = wq; K = 512;  N = 1536; t = b; }
    else if (b < 1024) { w = pw;   wT = wp; K = 512;  N = 512;  t = b - 768; }
    else if (b < 2048) { w = f1w;  wT = w1; K = 512;  N = 2048; t = b - 1024; }
    else               { w = f2w;  wT = w2; K = 2048; N = 512;  t = b - 2048; }
    int tx0 = N >> 5;
    int n0 = (t % tx0) * 32, k0 = (t / tx0) * 32;
    int tx = threadIdx.x, ty = threadIdx.y;
    for (int i = ty; i < 32; i += 8) s[i][tx] = w[(size_t)(k0 + i) * N + n0 + tx];
    __syncthreads();
    for (int i = ty; i < 32; i += 8) wT[(size_t)(n0 + i) * K + k0 + tx] = __float2half(s[tx][i]);
}

// ======================= LN: (C,L) fp32 -> (L,C) fp16, single gmem pass =======================
#define LNSTR 517
#define LN_SMEM_BYTES (32 * LNSTR * 4)
__global__ __launch_bounds__(256)
void ln_kernel(const float* __restrict__ in, const float* __restrict__ g,
               const float* __restrict__ b, __half* __restrict__ out)
{
    float* stg = (float*)smem_raw;     // [32][LNSTR]
    __shared__ float red[512];
    __shared__ float ms[32], rs[32];
    int tx = threadIdx.x & 31, ty = threadIdx.x >> 5;
    int tok = blockIdx.x * 32 + tx;
    float sum = 0.f, sq = 0.f;
    for (int c = ty; c < 512; c += 8) {
        float x = in[(size_t)c * TOK + tok];
        stg[tx * LNSTR + c] = x;
        sum += x; sq += x * x;
    }
    red[ty * 32 + tx] = sum; red[256 + ty * 32 + tx] = sq;
    __syncthreads();
    if (ty == 0) {
        float s = 0.f, q = 0.f;
        for (int j = 0; j < 8; j++) { s += red[j * 32 + tx]; q += red[256 + j * 32 + tx]; }
        float mean = s * (1.f / 512.f);
        float var  = q * (1.f / 512.f) - mean * mean;
        ms[tx] = mean; rs[tx] = rsqrtf(var + 1e-5f);
    }
    __syncthreads();
    size_t base = (size_t)blockIdx.x * 32 * 512;
#pragma unroll
    for (int i = 0; i < 8; i++) {
        int id = threadIdx.x + i * 256;
        int row = id >> 6, c8 = (id & 63) * 8;
        float mean = ms[row], rstd = rs[row];
        __half h[8];
#pragma unroll
        for (int j = 0; j < 8; j++) {
            int c = c8 + j;
            h[j] = __float2half((stg[row * LNSTR + c] - mean) * rstd * g[c] + b[c]);
        }
        *(uint4*)&out[base + (size_t)row * 512 + c8] = *(uint4*)h;
    }
}

// ======================= HMMA windowed attention + fused LePE =======================
// exp via ex2.approx.f16x2 (half the MUFU ops); lepe conv in half2 (half the LDS).
__global__ __launch_bounds__(128)
void attn_hmma(const __half* __restrict__ qkv, __half* __restrict__ att,
               const float* __restrict__ w0, const float* __restrict__ b0,
               const float* __restrict__ w1, const float* __restrict__ b1)
{
    __shared__ __half qs[128 * 40];
    __shared__ __half ks[128 * 40];
    __shared__ __half vt[32 * 136];    // V transposed: [channel][token] (for PV mma)
    __shared__ __half vs2[128 * 34];   // V token-major (lepe input)
    __shared__ __half lp[128 * 34];    // lepe: [token][channel]
    __shared__ __half2 swt2[144];      // conv weights [tap][chpair]
    __shared__ float sbv[32];
    const int tid = threadIdx.x;
    const int lane = tid & 31, warp = tid >> 5;
    const int bid = blockIdx.x;
    const int head = bid & 7;
    const int widx = (bid >> 3) & 255;
    const int branch = bid >> 11;
    const int d = widx >> 3, g = widx & 7;
    const int cc = branch * 256 + head * 32;

    // ---- conv weights: half2 per channel pair, [tap][pair] ----
    {
        const float* W  = branch ? w1 : w0;
        for (int idx = tid; idx < 144; idx += 128) {
            int tap = idx >> 4, p = idx & 15;
            int ch0 = head * 32 + 2 * p;
            swt2[idx] = __floats2half2_rn(W[ch0 * 9 + tap], W[(ch0 + 1) * 9 + tap]);
        }
        if (tid < 32) sbv[tid] = (branch ? b1 : b0)[head * 32 + tid];
    }

    // ---- load Q,K rows + V (both layouts) ----
    {
        int w = tid;
        int l = (branch == 0) ? d * 1024 + (w >> 2) * 32 + g * 4 + (w & 3)
                              : d * 1024 + g * 128 + w;
        const uint4* src = (const uint4*)&qkv[(size_t)l * 1536 + cc];
        uint4 qv[4], kv[4], vv[4];
#pragma unroll
        for (int i = 0; i < 4; i++) { qv[i] = src[i]; kv[i] = src[64 + i]; vv[i] = src[128 + i]; }
#pragma unroll
        for (int i = 0; i < 4; i++) {
            *(uint4*)&qs[w * 40 + i * 8] = qv[i];
            *(uint4*)&ks[w * 40 + i * 8] = kv[i];
        }
        const __half* vh = (const __half*)vv;
#pragma unroll
        for (int c = 0; c < 32; c++) vt[c * 136 + w] = vh[c];
        const __half2* vh2 = (const __half2*)vv;
#pragma unroll
        for (int i = 0; i < 16; i++) *(__half2*)&vs2[w * 34 + 2 * i] = vh2[i];
    }
    __syncthreads();

    // ---- fused LePE: depthwise 3x3, channel pairs in half2 ----
    {
        int w = tid;
        int i, j;
        const int Hs = branch ? 4 : 32;
        const int Ws = branch ? 32 : 4;
        if (branch == 0) { i = w >> 2; j = w & 3; }
        else             { i = w >> 5; j = w & 31; }
        float accx[16], accy[16];
#pragma unroll
        for (int p = 0; p < 16; p++) { accx[p] = sbv[2 * p]; accy[p] = sbv[2 * p + 1]; }
        for (int di = -1; di <= 1; di++) {
            int ii = i + di;
            if (ii < 0 || ii >= Hs) continue;
            for (int dj = -1; dj <= 1; dj++) {
                int jj = j + dj;
                if (jj < 0 || jj >= Ws) continue;
                int wp = (branch == 0) ? (ii * 4 + jj) : (ii * 32 + jj);
                int tap = (di + 1) * 3 + (dj + 1);
#pragma unroll
                for (int p = 0; p < 16; p++) {
                    float2 v  = __half22float2(*(__half2*)&vs2[wp * 34 + 2 * p]);
                    float2 wt = __half22float2(swt2[tap * 16 + p]);
                    accx[p] += wt.x * v.x;
                    accy[p] += wt.y * v.y;
                }
            }
        }
#pragma unroll
        for (int p = 0; p < 16; p++)
            *(__half2*)&lp[w * 34 + 2 * p] = __floats2half2_rn(accx[p], accy[p]);
    }
    __syncthreads();

    const uint32_t qb = smem_u32(qs);
    const uint32_t kb = smem_u32(ks);
    const uint32_t vb = smem_u32(vt);

    uint32_t aq[2][2][4];
#pragma unroll
    for (int mt = 0; mt < 2; mt++)
#pragma unroll
        for (int kk = 0; kk < 2; kk++) {
            int row = warp * 32 + mt * 16 + (lane & 15);
            int col = kk * 16 + ((lane >> 4) << 3);
            ldm4(aq[mt][kk], qb + (uint32_t)(row * 40 + col) * 2);
        }

    float oacc[2][4][4];
#pragma unroll
    for (int i = 0; i < 2; i++)
#pragma unroll
        for (int j = 0; j < 4; j++)
#pragma unroll
            for (int k = 0; k < 4; k++) oacc[i][j][k] = 0.f;
    float lsum[2][2] = {{0.f, 0.f}, {0.f, 0.f}};
    const float c2 = 0.17677669529663687f * 1.4426950408889634f;

#pragma unroll 1
    for (int ch = 0; ch < 2; ch++) {
        float s[2][8][4];
#pragma unroll
        for (int i = 0; i < 2; i++)
#pragma unroll
            for (int j = 0; j < 8; j++)
#pragma unroll
                for (int k = 0; k < 4; k++) s[i][j][k] = 0.f;
#pragma unroll
        for (int kk = 0; kk < 2; kk++) {
            uint32_t kf[8][2];
#pragma unroll
            for (int pg = 0; pg < 4; pg++) {
                int row = ch * 64 + pg * 16 + ((lane >> 4) & 1) * 8 + (lane & 7);
                int col = kk * 16 + ((lane >> 3) & 1) * 8;
                uint32_t t4[4];
                ldm4(t4, kb + (uint32_t)(row * 40 + col) * 2);
                kf[pg * 2][0] = t4[0]; kf[pg * 2][1] = t4[1];
                kf[pg * 2 + 1][0] = t4[2]; kf[pg * 2 + 1][1] = t4[3];
            }
#pragma unroll
            for (int mt = 0; mt < 2; mt++)
#pragma unroll
                for (int nt = 0; nt < 8; nt++)
                    mma16816(s[mt][nt], aq[mt][kk], kf[nt]);
        }
        uint32_t pa[2][4][4];
#pragma unroll
        for (int mt = 0; mt < 2; mt++)
#pragma unroll
            for (int j = 0; j < 4; j++)
#pragma unroll
                for (int q2 = 0; q2 < 2; q2++) {
                    float t0 = fminf(s[mt][2 * j + q2][0] * c2, 15.f);
                    float t1 = fminf(s[mt][2 * j + q2][1] * c2, 15.f);
                    float t2 = fminf(s[mt][2 * j + q2][2] * c2, 15.f);
                    float t3 = fminf(s[mt][2 * j + q2][3] * c2, 15.f);
                    uint32_t p01 = packh2(t0, t1);
                    uint32_t p23 = packh2(t2, t3);
                    asm("ex2.approx.f16x2 %0, %1;" : "=r"(p01) : "r"(p01));
                    asm("ex2.approx.f16x2 %0, %1;" : "=r"(p23) : "r"(p23));
                    pa[mt][j][q2 * 2 + 0] = p01;
                    pa[mt][j][q2 * 2 + 1] = p23;
                    float2 f01 = __half22float2(*(__half2*)&p01);
                    float2 f23 = __half22float2(*(__half2*)&p23);
                    lsum[mt][0] += f01.x + f01.y;
                    lsum[mt][1] += f23.x + f23.y;
                }
#pragma unroll
        for (int j = 0; j < 4; j++) {
            uint32_t vf[4][2];
#pragma unroll
            for (int pg = 0; pg < 2; pg++) {
                int row = pg * 16 + ((lane >> 4) & 1) * 8 + (lane & 7);
                int col = ch * 64 + j * 16 + ((lane >> 3) & 1) * 8;
                uint32_t t4[4];
                ldm4(t4, vb + (uint32_t)(row * 136 + col) * 2);
                vf[pg * 2][0] = t4[0]; vf[pg * 2][1] = t4[1];
                vf[pg * 2 + 1][0] = t4[2]; vf[pg * 2 + 1][1] = t4[3];
            }
#pragma unroll
            for (int mt = 0; mt < 2; mt++)
#pragma unroll
                for (int nt = 0; nt < 4; nt++)
                    mma16816(oacc[mt][nt], pa[mt][j], vf[nt]);
        }
    }

#pragma unroll
    for (int mt = 0; mt < 2; mt++)
#pragma unroll
        for (int h = 0; h < 2; h++) {
            float v = lsum[mt][h];
            v += __shfl_xor_sync(0xffffffffu, v, 1);
            v += __shfl_xor_sync(0xffffffffu, v, 2);
            lsum[mt][h] = 1.f / v;
        }

#pragma unroll
    for (int mt = 0; mt < 2; mt++) {
        int w0r = warp * 32 + mt * 16 + (lane >> 2);
#pragma unroll
        for (int h = 0; h < 2; h++) {
            int w = w0r + h * 8;
            int l = (branch == 0) ? d * 1024 + (w >> 2) * 32 + g * 4 + (w & 3)
                                  : d * 1024 + g * 128 + w;
            __half* ap = att + (size_t)l * 512 + cc;
            float inv = lsum[mt][h];
#pragma unroll
            for (int nt = 0; nt < 4; nt++) {
                int col = nt * 8 + 2 * (lane & 3);
                float2 lep = __half22float2(*(__half2*)&lp[w * 34 + col]);
                *(__half2*)(ap + col) = __floats2half2_rn(
                    lep.x + oacc[mt][nt][h * 2 + 0] * inv,
                    lep.y + oacc[mt][nt][h * 2 + 1] * inv);
            }
        }
    }
}

// ======================= launch =======================
extern "C" void kernel_launch(void* const* d_in, const int* in_sizes, int n_in,
                              void* d_out, int out_size)
{
    const float* x    = (const float*)d_in[0];
    const float* n1g  = (const float*)d_in[1];
    const float* n1b  = (const float*)d_in[2];
    const float* qkvw = (const float*)d_in[3];
    const float* l0w  = (const float*)d_in[4];
    const float* l0b  = (const float*)d_in[5];
    const float* l1w  = (const float*)d_in[6];
    const float* l1b  = (const float*)d_in[7];
    const float* pw   = (const float*)d_in[8];
    const float* pb   = (const float*)d_in[9];
    const float* n2g  = (const float*)d_in[10];
    const float* n2b  = (const float*)d_in[11];
    const float* f1w  = (const float*)d_in[12];
    const float* f1b  = (const float*)d_in[13];
    const float* f2w  = (const float*)d_in[14];
    const float* f2b  = (const float*)d_in[15];
    float* out = (float*)d_out;

    __half *img, *wq, *wp, *w1, *w2, *qkv, *att, *h2, *mid;
    float *xf;
    cudaGetSymbolAddress((void**)&img, g_img);
    cudaGetSymbolAddress((void**)&wq,  g_wq);
    cudaGetSymbolAddress((void**)&wp,  g_wp);
    cudaGetSymbolAddress((void**)&w1,  g_w1);
    cudaGetSymbolAddress((void**)&w2,  g_w2);
    cudaGetSymbolAddress((void**)&qkv, g_qkvh);
    cudaGetSymbolAddress((void**)&att, g_att);
    cudaGetSymbolAddress((void**)&xf,  g_xf);
    cudaGetSymbolAddress((void**)&h2,  g_h2);
    cudaGetSymbolAddress((void**)&mid, g_mid);

    cudaFuncSetAttribute(gemm_hmma<1>, cudaFuncAttributeMaxDynamicSharedMemorySize, GEMM_SMEM_BYTES);
    cudaFuncSetAttribute(gemm_hmma<2>, cudaFuncAttributeMaxDynamicSharedMemorySize, GEMM_SMEM_BYTES);
    cudaFuncSetAttribute(gemm_hmma<3>, cudaFuncAttributeMaxDynamicSharedMemorySize, GEMM_SMEM_BYTES);
    cudaFuncSetAttribute(ln_kernel,    cudaFuncAttributeMaxDynamicSharedMemorySize, LN_SMEM_BYTES);

    // merged weight transposes (fp32 -> fp16, (K,N) -> (N,K))
    wtrans_all<<<3072, dim3(32, 8)>>>(qkvw, wq, pw, wp, f1w, w1, f2w, w2);

    // LN1
    ln_kernel<<<TOK / 32, 256, LN_SMEM_BYTES>>>(x, n1g, n1b, img);
    // QKV GEMM -> fp16 row-major
    gemm_hmma<3><<<dim3(12, 256), 256, GEMM_SMEM_BYTES>>>(img, wq, nullptr, nullptr, qkv, TOK, 1536, 512);
    // attention with fused LePE -> att (pure store)
    attn_hmma<<<4096, 128>>>(qkv, att, l0w, l0b, l1w, l1b);
    // proj + bias + x residual -> xf (C,L) fp32
    gemm_hmma<1><<<dim3(4, 256), 256, GEMM_SMEM_BYTES>>>(att, wp, pb, x, xf, TOK, 0, 512);
    // LN2
    ln_kernel<<<TOK / 32, 256, LN_SMEM_BYTES>>>(xf, n2g, n2b, h2);
    // fc1 + bias + gelu -> mid fp16 row-major
    gemm_hmma<2><<<dim3(16, 256), 256, GEMM_SMEM_BYTES>>>(h2, w1, f1b, nullptr, mid, TOK, 2048, 512);
    // fc2 + bias + xf residual -> out (C,L) fp32
    gemm_hmma<1><<<dim3(4, 256), 256, GEMM_SMEM_BYTES>>>(mid, w2, f2b, xf, out, TOK, 0, 2048);
}

// round 17
// speedup vs baseline: 1.1539x; 1.0103x over previous
#include <cuda_runtime.h>
#include <cuda_fp16.h>
#include <math.h>
#include <stdint.h>

#define TOK 32768

// ======================= scratch (no cudaMalloc allowed) =======================
__device__ __half g_img[(size_t)TOK * 512];     // LN1 out, (L,C) row-major fp16
__device__ __half g_wq [(size_t)1536 * 512];    // qkv_w^T  (N,K) fp16
__device__ __half g_wp [(size_t)512 * 512];     // proj_w^T
__device__ __half g_w1 [(size_t)2048 * 512];    // fc1_w^T
__device__ __half g_w2 [(size_t)512 * 2048];    // fc2_w^T
__device__ __half g_qkvh[(size_t)TOK * 1536];   // (L,3C) fp16 row-major
__device__ __half g_att[(size_t)TOK * 512];     // lepe+attn out, (L,C) fp16
__device__ __half g_xfh[(size_t)512 * TOK];     // (C,L) fp16 col-major residual
__device__ __half g_h2 [(size_t)TOK * 512];     // LN2 out fp16 (L,C)
__device__ __half g_mid[(size_t)TOK * 2048];    // gelu(fc1) fp16 (L,2048)

// ======================= PTX helpers (sm_80-level only) =======================
__device__ __forceinline__ uint32_t smem_u32(const void* p) {
    uint32_t a;
    asm("{ .reg .u64 t; cvta.to.shared.u64 t, %1; cvt.u32.u64 %0, t; }" : "=r"(a) : "l"(p));
    return a;
}
__device__ __forceinline__ void ldm4(uint32_t* r, uint32_t a) {
    asm volatile("ldmatrix.sync.aligned.m8n8.x4.shared.b16 {%0,%1,%2,%3}, [%4];"
        : "=r"(r[0]), "=r"(r[1]), "=r"(r[2]), "=r"(r[3]) : "r"(a));
}
__device__ __forceinline__ void mma16816(float* d, const uint32_t* a, const uint32_t* b) {
    asm volatile("mma.sync.aligned.m16n8k16.row.col.f32.f16.f16.f32 "
        "{%0,%1,%2,%3}, {%4,%5,%6,%7}, {%8,%9}, {%0,%1,%2,%3};"
        : "+f"(d[0]), "+f"(d[1]), "+f"(d[2]), "+f"(d[3])
        : "r"(a[0]), "r"(a[1]), "r"(a[2]), "r"(a[3]), "r"(b[0]), "r"(b[1]));
}
__device__ __forceinline__ uint32_t packh2(float a, float b) {
    __half2 h = __floats2half2_rn(a, b);
    return *(uint32_t*)&h;
}
#define CP_ASYNC16(dst, src) \
    asm volatile("cp.async.cg.shared.global [%0], [%1], 16;" :: "r"(dst), "l"(src))
#define CP_COMMIT() asm volatile("cp.async.commit_group;" ::: "memory")
#define CP_WAIT1()  asm volatile("cp.async.wait_group 1;" ::: "memory")
#define CP_WAIT0()  asm volatile("cp.async.wait_group 0;" ::: "memory")

extern __shared__ char smem_raw[];

// ======================= HMMA GEMM (cp.async 2-stage, K-chunk 64) =======================
// C[M,N] = A[M,K](fp16 row-major) * Bw[N,K]^T (fp16, K contiguous per row)
// EPI 2: fp16 row-major out = gelu(acc + bias[n]), ld=ldo
// EPI 3: fp16 row-major out = acc, ld=ldo
// EPI 4: fp16 col-major out[n*M+m] = acc + bias[n] + resF32[n*M+m]
// EPI 5: fp32 col-major out[n*M+m] = acc + bias[n] + resF16[n*M+m]
#define TSTR 72                 // smem row stride in halves (144 B)
#define GSTG (128 * TSTR)       // halves per stage per matrix
#define GEMM_SMEM_BYTES (4 * GSTG * 2)   // 2 stages x (A+B) = 73728 B

template<int EPI>
__global__ __launch_bounds__(256)
void gemm_hmma(const __half* __restrict__ A, const __half* __restrict__ Bw,
               const float* __restrict__ bias, const void* __restrict__ resv,
               void* __restrict__ outp, int M, int ldo, int K)
{
    const int tid  = threadIdx.x;
    const int lane = tid & 31;
    const int warp = tid >> 5;
    const int wm = warp & 1;        // 2 warps along M
    const int wn = warp >> 1;       // 4 warps along N
    const int m0 = blockIdx.y * 128;
    const int n0 = blockIdx.x * 128;

    float acc[4][4][4];
#pragma unroll
    for (int i = 0; i < 4; i++)
#pragma unroll
        for (int j = 0; j < 4; j++)
#pragma unroll
            for (int k = 0; k < 4; k++) acc[i][j][k] = 0.f;

    const int chunks = K >> 6;           // K-chunk = 64
    const int grow = tid >> 3;           // 0..31 (4 groups of 32 rows)
    const int gcol = (tid & 7) * 8;      // halves: 8 lanes x 16B = full 128B row
    const uint32_t smb = smem_u32(smem_raw);

    auto issue = [&](int c) {
        int buf = c & 1;
        uint32_t sa = smb + (uint32_t)(buf * GSTG) * 2;
        uint32_t sb = smb + (uint32_t)((2 + buf) * GSTG) * 2;
#pragma unroll
        for (int i = 0; i < 4; i++) {
            int r = grow + i * 32;
            CP_ASYNC16(sa + (uint32_t)(r * TSTR + gcol) * 2,
                       &A [(size_t)(m0 + r) * K + c * 64 + gcol]);
            CP_ASYNC16(sb + (uint32_t)(r * TSTR + gcol) * 2,
                       &Bw[(size_t)(n0 + r) * K + c * 64 + gcol]);
        }
    };

    issue(0); CP_COMMIT();
    issue(1); CP_COMMIT();

    for (int c = 0; c < chunks; c++) {
        if (c + 1 < chunks) CP_WAIT1(); else CP_WAIT0();
        __syncthreads();

        const int buf = c & 1;
        const uint32_t baseA = smb + (uint32_t)(buf * GSTG) * 2;
        const uint32_t baseB = smb + (uint32_t)((2 + buf) * GSTG) * 2;
#pragma unroll
        for (int kk = 0; kk < 4; kk++) {
            uint32_t af[4][4];
#pragma unroll
            for (int mt = 0; mt < 4; mt++) {
                int row = wm * 64 + mt * 16 + (lane & 15);
                int col = kk * 16 + ((lane >> 4) << 3);
                ldm4(af[mt], baseA + (uint32_t)(row * TSTR + col) * 2);
            }
            uint32_t bf[4][2];
#pragma unroll
            for (int pr = 0; pr < 2; pr++) {
                int row = wn * 32 + pr * 16 + ((lane >> 4) & 1) * 8 + (lane & 7);
                int col = kk * 16 + ((lane >> 3) & 1) * 8;
                uint32_t t4[4];
                ldm4(t4, baseB + (uint32_t)(row * TSTR + col) * 2);
                bf[pr * 2][0] = t4[0]; bf[pr * 2][1] = t4[1];
                bf[pr * 2 + 1][0] = t4[2]; bf[pr * 2 + 1][1] = t4[3];
            }
#pragma unroll
            for (int mt = 0; mt < 4; mt++)
#pragma unroll
                for (int nt = 0; nt < 4; nt++)
                    mma16816(acc[mt][nt], af[mt], bf[nt]);
        }
        if (c + 2 < chunks) {
            __syncthreads();          // all reads of buf done before overwrite
            issue(c + 2); CP_COMMIT();
        }
    }

    // ---------------- epilogue ----------------
#pragma unroll
    for (int mt = 0; mt < 4; mt++) {
        int r = m0 + wm * 64 + mt * 16 + (lane >> 2);
#pragma unroll
        for (int nt = 0; nt < 4; nt++) {
            int cN = n0 + wn * 32 + nt * 8 + 2 * (lane & 3);
            float v0 = acc[mt][nt][0], v1 = acc[mt][nt][1];
            float v2 = acc[mt][nt][2], v3 = acc[mt][nt][3];
            if (EPI != 3) {
                float b0 = __ldg(&bias[cN]), b1 = __ldg(&bias[cN + 1]);
                v0 += b0; v1 += b1; v2 += b0; v3 += b1;
            }
            if (EPI == 2) {
                v0 = 0.5f * v0 * (1.f + erff(v0 * 0.70710678118654752f));
                v1 = 0.5f * v1 * (1.f + erff(v1 * 0.70710678118654752f));
                v2 = 0.5f * v2 * (1.f + erff(v2 * 0.70710678118654752f));
                v3 = 0.5f * v3 * (1.f + erff(v3 * 0.70710678118654752f));
            }
            if (EPI == 4) {
                const float* resf = (const float*)resv;
                __half* o = (__half*)outp;
                size_t i00 = (size_t)cN * M + r;
                size_t i01 = (size_t)(cN + 1) * M + r;
                o[i00]     = __float2half(v0 + __ldg(&resf[i00]));
                o[i01]     = __float2half(v1 + __ldg(&resf[i01]));
                o[i00 + 8] = __float2half(v2 + __ldg(&resf[i00 + 8]));
                o[i01 + 8] = __float2half(v3 + __ldg(&resf[i01 + 8]));
            } else if (EPI == 5) {
                const __half* resh = (const __half*)resv;
                float* o = (float*)outp;
                size_t i00 = (size_t)cN * M + r;
                size_t i01 = (size_t)(cN + 1) * M + r;
                o[i00]     = v0 + __half2float(__ldg(&resh[i00]));
                o[i01]     = v1 + __half2float(__ldg(&resh[i01]));
                o[i00 + 8] = v2 + __half2float(__ldg(&resh[i00 + 8]));
                o[i01 + 8] = v3 + __half2float(__ldg(&resh[i01 + 8]));
            } else {
                __half* o = (__half*)outp;
                *(__half2*)&o[(size_t)r * ldo + cN]       = __floats2half2_rn(v0, v1);
                *(__half2*)&o[(size_t)(r + 8) * ldo + cN] = __floats2half2_rn(v2, v3);
            }
        }
    }
}

// ======================= merged weight transpose + fp16 convert =======================
__global__ void wtrans_all(const float* __restrict__ qkvw, __half* __restrict__ wq,
                           const float* __restrict__ pw,   __half* __restrict__ wp,
                           const float* __restrict__ f1w,  __half* __restrict__ w1,
                           const float* __restrict__ f2w,  __half* __restrict__ w2)
{
    __shared__ float s[32][33];
    int b = blockIdx.x;
    const float* w; __half* wT; int K, N, t;
    if (b < 768)       { w = qkvw; wT = wq; K = 512;  N = 1536; t = b; }
    else if (b < 1024) { w = pw;   wT = wp; K = 512;  N = 512;  t = b - 768; }
    else if (b < 2048) { w = f1w;  wT = w1; K = 512;  N = 2048; t = b - 1024; }
    else               { w = f2w;  wT = w2; K = 2048; N = 512;  t = b - 2048; }
    int tx0 = N >> 5;
    int n0 = (t % tx0) * 32, k0 = (t / tx0) * 32;
    int tx = threadIdx.x, ty = threadIdx.y;
    for (int i = ty; i < 32; i += 8) s[i][tx] = w[(size_t)(k0 + i) * N + n0 + tx];
    __syncthreads();
    for (int i = ty; i < 32; i += 8) wT[(size_t)(n0 + i) * K + k0 + tx] = __float2half(s[tx][i]);
}

// ======================= LN: (C,L) T -> (L,C) fp16, single gmem pass =======================
#define LNSTR 517
#define LN_SMEM_BYTES (32 * LNSTR * 4)
template<typename T>
__global__ __launch_bounds__(256)
void ln_kernel(const T* __restrict__ in, const float* __restrict__ g,
               const float* __restrict__ b, __half* __restrict__ out)
{
    float* stg = (float*)smem_raw;     // [32][LNSTR]
    __shared__ float red[512];
    __shared__ float ms[32], rs[32];
    int tx = threadIdx.x & 31, ty = threadIdx.x >> 5;
    int tok = blockIdx.x * 32 + tx;
    float sum = 0.f, sq = 0.f;
    for (int c = ty; c < 512; c += 8) {
        float x = (float)in[(size_t)c * TOK + tok];
        stg[tx * LNSTR + c] = x;
        sum += x; sq += x * x;
    }
    red[ty * 32 + tx] = sum; red[256 + ty * 32 + tx] = sq;
    __syncthreads();
    if (ty == 0) {
        float s = 0.f, q = 0.f;
        for (int j = 0; j < 8; j++) { s += red[j * 32 + tx]; q += red[256 + j * 32 + tx]; }
        float mean = s * (1.f / 512.f);
        float var  = q * (1.f / 512.f) - mean * mean;
        ms[tx] = mean; rs[tx] = rsqrtf(var + 1e-5f);
    }
    __syncthreads();
    size_t base = (size_t)blockIdx.x * 32 * 512;
#pragma unroll
    for (int i = 0; i < 8; i++) {
        int id = threadIdx.x + i * 256;
        int row = id >> 6, c8 = (id & 63) * 8;
        float mean = ms[row], rstd = rs[row];
        __half h[8];
#pragma unroll
        for (int j = 0; j < 8; j++) {
            int c = c8 + j;
            h[j] = __float2half((stg[row * LNSTR + c] - mean) * rstd * g[c] + b[c]);
        }
        *(uint4*)&out[base + (size_t)row * 512 + c8] = *(uint4*)h;
    }
}

// ======================= HMMA windowed attention + fused LePE =======================
// exp via ex2.approx.f16x2 (half the MUFU ops); lepe conv in half2 (half the LDS).
__global__ __launch_bounds__(128)
void attn_hmma(const __half* __restrict__ qkv, __half* __restrict__ att,
               const float* __restrict__ w0, const float* __restrict__ b0,
               const float* __restrict__ w1, const float* __restrict__ b1)
{
    __shared__ __half qs[128 * 40];
    __shared__ __half ks[128 * 40];
    __shared__ __half vt[32 * 136];    // V transposed: [channel][token] (for PV mma)
    __shared__ __half vs2[128 * 34];   // V token-major (lepe input)
    __shared__ __half lp[128 * 34];    // lepe: [token][channel]
    __shared__ __half2 swt2[144];      // conv weights [tap][chpair]
    __shared__ float sbv[32];
    const int tid = threadIdx.x;
    const int lane = tid & 31, warp = tid >> 5;
    const int bid = blockIdx.x;
    const int head = bid & 7;
    const int widx = (bid >> 3) & 255;
    const int branch = bid >> 11;
    const int d = widx >> 3, g = widx & 7;
    const int cc = branch * 256 + head * 32;

    // ---- conv weights: half2 per channel pair, [tap][pair] ----
    {
        const float* W  = branch ? w1 : w0;
        for (int idx = tid; idx < 144; idx += 128) {
            int tap = idx >> 4, p = idx & 15;
            int ch0 = head * 32 + 2 * p;
            swt2[idx] = __floats2half2_rn(W[ch0 * 9 + tap], W[(ch0 + 1) * 9 + tap]);
        }
        if (tid < 32) sbv[tid] = (branch ? b1 : b0)[head * 32 + tid];
    }

    // ---- load Q,K rows + V (both layouts) ----
    {
        int w = tid;
        int l = (branch == 0) ? d * 1024 + (w >> 2) * 32 + g * 4 + (w & 3)
                              : d * 1024 + g * 128 + w;
        const uint4* src = (const uint4*)&qkv[(size_t)l * 1536 + cc];
        uint4 qv[4], kv[4], vv[4];
#pragma unroll
        for (int i = 0; i < 4; i++) { qv[i] = src[i]; kv[i] = src[64 + i]; vv[i] = src[128 + i]; }
#pragma unroll
        for (int i = 0; i < 4; i++) {
            *(uint4*)&qs[w * 40 + i * 8] = qv[i];
            *(uint4*)&ks[w * 40 + i * 8] = kv[i];
        }
        const __half* vh = (const __half*)vv;
#pragma unroll
        for (int c = 0; c < 32; c++) vt[c * 136 + w] = vh[c];
        const __half2* vh2 = (const __half2*)vv;
#pragma unroll
        for (int i = 0; i < 16; i++) *(__half2*)&vs2[w * 34 + 2 * i] = vh2[i];
    }
    __syncthreads();

    // ---- fused LePE: depthwise 3x3, channel pairs in half2 ----
    {
        int w = tid;
        int i, j;
        const int Hs = branch ? 4 : 32;
        const int Ws = branch ? 32 : 4;
        if (branch == 0) { i = w >> 2; j = w & 3; }
        else             { i = w >> 5; j = w & 31; }
        float accx[16], accy[16];
#pragma unroll
        for (int p = 0; p < 16; p++) { accx[p] = sbv[2 * p]; accy[p] = sbv[2 * p + 1]; }
        for (int di = -1; di <= 1; di++) {
            int ii = i + di;
            if (ii < 0 || ii >= Hs) continue;
            for (int dj = -1; dj <= 1; dj++) {
                int jj = j + dj;
                if (jj < 0 || jj >= Ws) continue;
                int wp = (branch == 0) ? (ii * 4 + jj) : (ii * 32 + jj);
                int tap = (di + 1) * 3 + (dj + 1);
#pragma unroll
                for (int p = 0; p < 16; p++) {
                    float2 v  = __half22float2(*(__half2*)&vs2[wp * 34 + 2 * p]);
                    float2 wt = __half22float2(swt2[tap * 16 + p]);
                    accx[p] += wt.x * v.x;
                    accy[p] += wt.y * v.y;
                }
            }
        }
#pragma unroll
        for (int p = 0; p < 16; p++)
            *(__half2*)&lp[w * 34 + 2 * p] = __floats2half2_rn(accx[p], accy[p]);
    }
    __syncthreads();

    const uint32_t qb = smem_u32(qs);
    const uint32_t kb = smem_u32(ks);
    const uint32_t vb = smem_u32(vt);

    uint32_t aq[2][2][4];
#pragma unroll
    for (int mt = 0; mt < 2; mt++)
#pragma unroll
        for (int kk = 0; kk < 2; kk++) {
            int row = warp * 32 + mt * 16 + (lane & 15);
            int col = kk * 16 + ((lane >> 4) << 3);
            ldm4(aq[mt][kk], qb + (uint32_t)(row * 40 + col) * 2);
        }

    float oacc[2][4][4];
#pragma unroll
    for (int i = 0; i < 2; i++)
#pragma unroll
        for (int j = 0; j < 4; j++)
#pragma unroll
            for (int k = 0; k < 4; k++) oacc[i][j][k] = 0.f;
    float lsum[2][2] = {{0.f, 0.f}, {0.f, 0.f}};
    const float c2 = 0.17677669529663687f * 1.4426950408889634f;

#pragma unroll 1
    for (int ch = 0; ch < 2; ch++) {
        float s[2][8][4];
#pragma unroll
        for (int i = 0; i < 2; i++)
#pragma unroll
            for (int j = 0; j < 8; j++)
#pragma unroll
                for (int k = 0; k < 4; k++) s[i][j][k] = 0.f;
#pragma unroll
        for (int kk = 0; kk < 2; kk++) {
            uint32_t kf[8][2];
#pragma unroll
            for (int pg = 0; pg < 4; pg++) {
                int row = ch * 64 + pg * 16 + ((lane >> 4) & 1) * 8 + (lane & 7);
                int col = kk * 16 + ((lane >> 3) & 1) * 8;
                uint32_t t4[4];
                ldm4(t4, kb + (uint32_t)(row * 40 + col) * 2);
                kf[pg * 2][0] = t4[0]; kf[pg * 2][1] = t4[1];
                kf[pg * 2 + 1][0] = t4[2]; kf[pg * 2 + 1][1] = t4[3];
            }
#pragma unroll
            for (int mt = 0; mt < 2; mt++)
#pragma unroll
                for (int nt = 0; nt < 8; nt++)
                    mma16816(s[mt][nt], aq[mt][kk], kf[nt]);
        }
        uint32_t pa[2][4][4];
#pragma unroll
        for (int mt = 0; mt < 2; mt++)
#pragma unroll
            for (int j = 0; j < 4; j++)
#pragma unroll
                for (int q2 = 0; q2 < 2; q2++) {
                    float t0 = fminf(s[mt][2 * j + q2][0] * c2, 15.f);
                    float t1 = fminf(s[mt][2 * j + q2][1] * c2, 15.f);
                    float t2 = fminf(s[mt][2 * j + q2][2] * c2, 15.f);
                    float t3 = fminf(s[mt][2 * j + q2][3] * c2, 15.f);
                    uint32_t p01 = packh2(t0, t1);
                    uint32_t p23 = packh2(t2, t3);
                    asm("ex2.approx.f16x2 %0, %1;" : "=r"(p01) : "r"(p01));
                    asm("ex2.approx.f16x2 %0, %1;" : "=r"(p23) : "r"(p23));
                    pa[mt][j][q2 * 2 + 0] = p01;
                    pa[mt][j][q2 * 2 + 1] = p23;
                    float2 f01 = __half22float2(*(__half2*)&p01);
                    float2 f23 = __half22float2(*(__half2*)&p23);
                    lsum[mt][0] += f01.x + f01.y;
                    lsum[mt][1] += f23.x + f23.y;
                }
#pragma unroll
        for (int j = 0; j < 4; j++) {
            uint32_t vf[4][2];
#pragma unroll
            for (int pg = 0; pg < 2; pg++) {
                int row = pg * 16 + ((lane >> 4) & 1) * 8 + (lane & 7);
                int col = ch * 64 + j * 16 + ((lane >> 3) & 1) * 8;
                uint32_t t4[4];
                ldm4(t4, vb + (uint32_t)(row * 136 + col) * 2);
                vf[pg * 2][0] = t4[0]; vf[pg * 2][1] = t4[1];
                vf[pg * 2 + 1][0] = t4[2]; vf[pg * 2 + 1][1] = t4[3];
            }
#pragma unroll
            for (int mt = 0; mt < 2; mt++)
#pragma unroll
                for (int nt = 0; nt < 4; nt++)
                    mma16816(oacc[mt][nt], pa[mt][j], vf[nt]);
        }
    }

#pragma unroll
    for (int mt = 0; mt < 2; mt++)
#pragma unroll
        for (int h = 0; h < 2; h++) {
            float v = lsum[mt][h];
            v += __shfl_xor_sync(0xffffffffu, v, 1);
            v += __shfl_xor_sync(0xffffffffu, v, 2);
            lsum[mt][h] = 1.f / v;
        }

#pragma unroll
    for (int mt = 0; mt < 2; mt++) {
        int w0r = warp * 32 + mt * 16 + (lane >> 2);
#pragma unroll
        for (int h = 0; h < 2; h++) {
            int w = w0r + h * 8;
            int l = (branch == 0) ? d * 1024 + (w >> 2) * 32 + g * 4 + (w & 3)
                                  : d * 1024 + g * 128 + w;
            __half* ap = att + (size_t)l * 512 + cc;
            float inv = lsum[mt][h];
#pragma unroll
            for (int nt = 0; nt < 4; nt++) {
                int col = nt * 8 + 2 * (lane & 3);
                float2 lep = __half22float2(*(__half2*)&lp[w * 34 + col]);
                *(__half2*)(ap + col) = __floats2half2_rn(
                    lep.x + oacc[mt][nt][h * 2 + 0] * inv,
                    lep.y + oacc[mt][nt][h * 2 + 1] * inv);
            }
        }
    }
}

// ======================= launch =======================
extern "C" void kernel_launch(void* const* d_in, const int* in_sizes, int n_in,
                              void* d_out, int out_size)
{
    const float* x    = (const float*)d_in[0];
    const float* n1g  = (const float*)d_in[1];
    const float* n1b  = (const float*)d_in[2];
    const float* qkvw = (const float*)d_in[3];
    const float* l0w  = (const float*)d_in[4];
    const float* l0b  = (const float*)d_in[5];
    const float* l1w  = (const float*)d_in[6];
    const float* l1b  = (const float*)d_in[7];
    const float* pw   = (const float*)d_in[8];
    const float* pb   = (const float*)d_in[9];
    const float* n2g  = (const float*)d_in[10];
    const float* n2b  = (const float*)d_in[11];
    const float* f1w  = (const float*)d_in[12];
    const float* f1b  = (const float*)d_in[13];
    const float* f2w  = (const float*)d_in[14];
    const float* f2b  = (const float*)d_in[15];
    float* out = (float*)d_out;

    __half *img, *wq, *wp, *w1, *w2, *qkv, *att, *xfh, *h2, *mid;
    cudaGetSymbolAddress((void**)&img, g_img);
    cudaGetSymbolAddress((void**)&wq,  g_wq);
    cudaGetSymbolAddress((void**)&wp,  g_wp);
    cudaGetSymbolAddress((void**)&w1,  g_w1);
    cudaGetSymbolAddress((void**)&w2,  g_w2);
    cudaGetSymbolAddress((void**)&qkv, g_qkvh);
    cudaGetSymbolAddress((void**)&att, g_att);
    cudaGetSymbolAddress((void**)&xfh, g_xfh);
    cudaGetSymbolAddress((void**)&h2,  g_h2);
    cudaGetSymbolAddress((void**)&mid, g_mid);

    cudaFuncSetAttribute(gemm_hmma<2>, cudaFuncAttributeMaxDynamicSharedMemorySize, GEMM_SMEM_BYTES);
    cudaFuncSetAttribute(gemm_hmma<3>, cudaFuncAttributeMaxDynamicSharedMemorySize, GEMM_SMEM_BYTES);
    cudaFuncSetAttribute(gemm_hmma<4>, cudaFuncAttributeMaxDynamicSharedMemorySize, GEMM_SMEM_BYTES);
    cudaFuncSetAttribute(gemm_hmma<5>, cudaFuncAttributeMaxDynamicSharedMemorySize, GEMM_SMEM_BYTES);
    cudaFuncSetAttribute(ln_kernel<float>,  cudaFuncAttributeMaxDynamicSharedMemorySize, LN_SMEM_BYTES);
    cudaFuncSetAttribute(ln_kernel<__half>, cudaFuncAttributeMaxDynamicSharedMemorySize, LN_SMEM_BYTES);

    // merged weight transposes (fp32 -> fp16, (K,N) -> (N,K))
    wtrans_all<<<3072, dim3(32, 8)>>>(qkvw, wq, pw, wp, f1w, w1, f2w, w2);

    // LN1 (fp32 in)
    ln_kernel<float><<<TOK / 32, 256, LN_SMEM_BYTES>>>(x, n1g, n1b, img);
    // QKV GEMM -> fp16 row-major
    gemm_hmma<3><<<dim3(12, 256), 256, GEMM_SMEM_BYTES>>>(img, wq, nullptr, nullptr, qkv, TOK, 1536, 512);
    // attention with fused LePE -> att (pure store)
    attn_hmma<<<4096, 128>>>(qkv, att, l0w, l0b, l1w, l1b);
    // proj + bias + x residual -> xf (C,L) fp16
    gemm_hmma<4><<<dim3(4, 256), 256, GEMM_SMEM_BYTES>>>(att, wp, pb, x, xfh, TOK, 0, 512);
    // LN2 (fp16 in)
    ln_kernel<__half><<<TOK / 32, 256, LN_SMEM_BYTES>>>(xfh, n2g, n2b, h2);
    // fc1 + bias + gelu -> mid fp16 row-major
    gemm_hmma<2><<<dim3(16, 256), 256, GEMM_SMEM_BYTES>>>(h2, w1, f1b, nullptr, mid, TOK, 2048, 512);
    // fc2 + bias + xf(fp16) residual -> out (C,L) fp32
    gemm_hmma<5><<<dim3(4, 256), 256, GEMM_SMEM_BYTES>>>(mid, w2, f2b, xfh, out, TOK, 0, 2048);
}